// round 9
// baseline (speedup 1.0000x reference)
#include <cuda_runtime.h>

#define BB   4
#define NIN  128
#define NOUT 128
#define NN   256

// Fused kernel, i-split: one block per (b, o, half).
//   Phase 1 (proj): thread j computes Pi[b,o,j], Pj[b,o,j] into smem
//                   (recomputed per half — cheap, node is L2-resident).
//   Phase 2 (expand): thread (sub, j4) streams 32 rows i of the output:
//       out[b,o,i,j] = adj[b,i,j] * (i==j ? Pi[j] : Pj[j])
// First 4 adj rows are prefetched BEFORE the proj loop so their latency
// hides under the GEMV. Output stores are evict-first (__stcs) so the
// 134MB stream doesn't evict hot adj/node/P lines from L2.
__global__ void __launch_bounds__(256, 5)
fused_kernel(const float* __restrict__ node,
             const float* __restrict__ Wi,
             const float* __restrict__ Wj,
             const float4* __restrict__ adj,
             float4* __restrict__ out) {
    __shared__ float s_pi[NN];
    __shared__ __align__(16) float s_pj[NN];

    const int t    = threadIdx.x;                 // 0..255
    const int half = blockIdx.x & 1;              // i-half
    const int o    = (blockIdx.x >> 1) & (NOUT - 1);
    const int b    = blockIdx.x >> 8;

    const int j4  = t & 63;                       // float4 column index
    const int sub = t >> 6;                       // 0..3
    const int i_base = (half << 7) + (sub << 5);  // this thread's 32 rows

    const float4* adj_b  = adj + ((unsigned)b << 14);
    float4*       out_bo = out + (((unsigned)(b << 7) + o) << 14);

    // ---- Prefetch first 4 adj rows (independent of proj) ----
    float4 pf0 = __ldg(&adj_b[((i_base + 0) << 6) + j4]);
    float4 pf1 = __ldg(&adj_b[((i_base + 1) << 6) + j4]);
    float4 pf2 = __ldg(&adj_b[((i_base + 2) << 6) + j4]);
    float4 pf3 = __ldg(&adj_b[((i_base + 3) << 6) + j4]);

    // ---- Phase 1: Pi[j], Pj[j] for j = t ----
    {
        const float* np = node + b * NIN * NN + t;
        const float* wi = Wi + o * NIN;
        const float* wj = Wj + o * NIN;
        float ai = 0.0f, aj = 0.0f;
#pragma unroll 8
        for (int c = 0; c < NIN; ++c) {
            const float nv = __ldg(&np[c * NN]);
            ai = fmaf(__ldg(&wi[c]), nv, ai);
            aj = fmaf(__ldg(&wj[c]), nv, aj);
        }
        s_pi[t] = ai;
        s_pj[t] = aj;
    }
    __syncthreads();

    const float4 p = reinterpret_cast<const float4*>(s_pj)[j4];

    // ---- Phase 2, group 0 (rows i_base..i_base+3) from prefetch ----
    {
        const int i0 = i_base;
        float4 r0, r1, r2, r3;
        r0.x = pf0.x * p.x; r0.y = pf0.y * p.y; r0.z = pf0.z * p.z; r0.w = pf0.w * p.w;
        r1.x = pf1.x * p.x; r1.y = pf1.y * p.y; r1.z = pf1.z * p.z; r1.w = pf1.w * p.w;
        r2.x = pf2.x * p.x; r2.y = pf2.y * p.y; r2.z = pf2.z * p.z; r2.w = pf2.w * p.w;
        r3.x = pf3.x * p.x; r3.y = pf3.y * p.y; r3.z = pf3.z * p.z; r3.w = pf3.w * p.w;
        if ((i0 >> 2) == j4) {
            r0.x = pf0.x * s_pi[i0 + 0];
            r1.y = pf1.y * s_pi[i0 + 1];
            r2.z = pf2.z * s_pi[i0 + 2];
            r3.w = pf3.w * s_pi[i0 + 3];
        }
        __stcs(&out_bo[((i0 + 0) << 6) + j4], r0);
        __stcs(&out_bo[((i0 + 1) << 6) + j4], r1);
        __stcs(&out_bo[((i0 + 2) << 6) + j4], r2);
        __stcs(&out_bo[((i0 + 3) << 6) + j4], r3);
    }

    // ---- Phase 2, groups 1..7 (remaining 28 rows) ----
#pragma unroll 2
    for (int g = 1; g < 8; ++g) {
        const int i0 = i_base + (g << 2);

        const float4 a0 = __ldg(&adj_b[((i0 + 0) << 6) + j4]);
        const float4 a1 = __ldg(&adj_b[((i0 + 1) << 6) + j4]);
        const float4 a2 = __ldg(&adj_b[((i0 + 2) << 6) + j4]);
        const float4 a3 = __ldg(&adj_b[((i0 + 3) << 6) + j4]);

        float4 r0, r1, r2, r3;
        r0.x = a0.x * p.x; r0.y = a0.y * p.y; r0.z = a0.z * p.z; r0.w = a0.w * p.w;
        r1.x = a1.x * p.x; r1.y = a1.y * p.y; r1.z = a1.z * p.z; r1.w = a1.w * p.w;
        r2.x = a2.x * p.x; r2.y = a2.y * p.y; r2.z = a2.z * p.z; r2.w = a2.w * p.w;
        r3.x = a3.x * p.x; r3.y = a3.y * p.y; r3.z = a3.z * p.z; r3.w = a3.w * p.w;

        if ((i0 >> 2) == j4) {
            r0.x = a0.x * s_pi[i0 + 0];
            r1.y = a1.y * s_pi[i0 + 1];
            r2.z = a2.z * s_pi[i0 + 2];
            r3.w = a3.w * s_pi[i0 + 3];
        }

        __stcs(&out_bo[((i0 + 0) << 6) + j4], r0);
        __stcs(&out_bo[((i0 + 1) << 6) + j4], r1);
        __stcs(&out_bo[((i0 + 2) << 6) + j4], r2);
        __stcs(&out_bo[((i0 + 3) << 6) + j4], r3);
    }
}

extern "C" void kernel_launch(void* const* d_in, const int* in_sizes, int n_in,
                              void* d_out, int out_size) {
    const float* adj  = (const float*)d_in[0];  // [B,1,N,N]
    const float* node = (const float*)d_in[1];  // [B,NIN,N]
    const float* Wi   = (const float*)d_in[2];  // [NOUT,NIN]
    const float* Wj   = (const float*)d_in[3];  // [NOUT,NIN]
    float* out = (float*)d_out;                 // [B,NOUT,N,N]

    (void)in_sizes; (void)n_in; (void)out_size;

    fused_kernel<<<BB * NOUT * 2, 256>>>(node, Wi, Wj,
                                         (const float4*)adj, (float4*)out);
}

// round 10
// speedup vs baseline: 1.2374x; 1.2374x over previous
#include <cuda_runtime.h>

#define BB   4
#define NIN  128
#define NOUT 128
#define NN   256

// Global scratch for Pi = Wi@node, Pj = Wj@node (512KB each; allocation-free).
__device__ __align__(16) float g_pi[BB * NOUT * NN];
__device__ __align__(16) float g_pj[BB * NOUT * NN];

// ---------------------------------------------------------------------------
// Kernel 1: projections. grid = BB * 32 (o-groups of 4), block = 256.
// Thread (j4 = t&63, ol = t>>6) computes Pi/Pj float4 for o = og*4+ol.
// Each block reads node[b] exactly once (threads with same j4 dedup in L1),
// so node L2 traffic is only 128 blocks * 128KB = 16MB.
// ---------------------------------------------------------------------------
__global__ void __launch_bounds__(256)
proj_kernel(const float* __restrict__ node,
            const float* __restrict__ Wi,
            const float* __restrict__ Wj) {
    const int t  = threadIdx.x;
    const int j4 = t & 63;
    const int ol = t >> 6;                       // 0..3
    const int og = blockIdx.x & 31;              // o-group
    const int b  = blockIdx.x >> 5;
    const int o  = (og << 2) + ol;

    const float4* node4 = (const float4*)(node + b * NIN * NN);  // [c][j4]
    const float* wi = Wi + o * NIN;
    const float* wj = Wj + o * NIN;

    float4 ai = make_float4(0.f, 0.f, 0.f, 0.f);
    float4 aj = make_float4(0.f, 0.f, 0.f, 0.f);
#pragma unroll 8
    for (int c = 0; c < NIN; ++c) {
        const float4 nv = __ldg(&node4[(c << 6) + j4]);
        const float wiv = __ldg(&wi[c]);
        const float wjv = __ldg(&wj[c]);
        ai.x = fmaf(wiv, nv.x, ai.x); ai.y = fmaf(wiv, nv.y, ai.y);
        ai.z = fmaf(wiv, nv.z, ai.z); ai.w = fmaf(wiv, nv.w, ai.w);
        aj.x = fmaf(wjv, nv.x, aj.x); aj.y = fmaf(wjv, nv.y, aj.y);
        aj.z = fmaf(wjv, nv.z, aj.z); aj.w = fmaf(wjv, nv.w, aj.w);
    }
    const int off = ((b << 7) + o) << 6;         // float4 row offset
    reinterpret_cast<float4*>(g_pi)[off + j4] = ai;
    reinterpret_cast<float4*>(g_pj)[off + j4] = aj;
}

// ---------------------------------------------------------------------------
// Kernel 2: expand. grid = BB * 8 * 32 = 1024 blocks, block = 256.
// Block = (b, i-block of 32 rows, o-group of 4). Stages the 32x256 adj slice
// in 32KB smem once, then streams 4 output tiles from it:
//     out[b,o,i,j] = adj[b,i,j] * (i==j ? Pi[b,o,j] : Pj[b,o,j])
// o-group is the fastest grid dim so concurrent blocks share adj in L2.
// Stores are evict-first: the 134MB output stream must not evict adj/P.
// ---------------------------------------------------------------------------
__global__ void __launch_bounds__(256, 5)
expand_kernel(const float4* __restrict__ adj,
              float4* __restrict__ out) {
    __shared__ __align__(16) float4 s_adj[32 * 64];   // 32 rows x 64 float4 = 32KB

    const int t    = threadIdx.x;
    const int og   = blockIdx.x & 31;                 // o-group (fastest)
    const int iblk = (blockIdx.x >> 5) & 7;
    const int b    = blockIdx.x >> 8;

    // ---- Stage adj slice (rows iblk*32 .. +31) into smem, coalesced ----
    const float4* adj_src = adj + ((unsigned)b << 14) + ((unsigned)iblk << 11);
#pragma unroll
    for (int k = 0; k < 8; ++k) {
        const int idx = t + (k << 8);
        s_adj[idx] = __ldg(&adj_src[idx]);
    }
    __syncthreads();

    const int j4  = t & 63;
    const int sub = t >> 6;                           // 0..3 -> 8 rows each
    const int i0g = (iblk << 5) + (sub << 3);         // first global row

    const float4* pj4 = reinterpret_cast<const float4*>(g_pj);

#pragma unroll
    for (int ol = 0; ol < 4; ++ol) {
        const int o      = (og << 2) + ol;
        const int po     = (b << 7) + o;
        const float4 p   = __ldg(&pj4[(po << 6) + j4]);
        float4* out_o    = out + ((unsigned)po << 14);

#pragma unroll
        for (int rr = 0; rr < 8; ++rr) {
            const int rl = (sub << 3) + rr;           // local row 0..31
            const int i  = i0g + rr;                  // global row

            const float4 a = s_adj[(rl << 6) + j4];
            float4 r;
            r.x = a.x * p.x; r.y = a.y * p.y;
            r.z = a.z * p.z; r.w = a.w * p.w;

            if ((i >> 2) == j4) {                     // diagonal in this float4
                const float piv = __ldg(&g_pi[(po << 8) + i]);
                const int lane = i & 3;
                if      (lane == 0) r.x = a.x * piv;
                else if (lane == 1) r.y = a.y * piv;
                else if (lane == 2) r.z = a.z * piv;
                else                r.w = a.w * piv;
            }

            __stcs(&out_o[(i << 6) + j4], r);
        }
    }
}

extern "C" void kernel_launch(void* const* d_in, const int* in_sizes, int n_in,
                              void* d_out, int out_size) {
    const float* adj  = (const float*)d_in[0];  // [B,1,N,N]
    const float* node = (const float*)d_in[1];  // [B,NIN,N]
    const float* Wi   = (const float*)d_in[2];  // [NOUT,NIN]
    const float* Wj   = (const float*)d_in[3];  // [NOUT,NIN]
    float* out = (float*)d_out;                 // [B,NOUT,N,N]

    (void)in_sizes; (void)n_in; (void)out_size;

    proj_kernel<<<BB * 32, 256>>>(node, Wi, Wj);
    expand_kernel<<<BB * 8 * 32, 256>>>((const float4*)adj, (float4*)out);
}

// round 13
// speedup vs baseline: 1.4755x; 1.1924x over previous
#include <cuda_runtime.h>

#define BB   4
#define NIN  128
#define NOUT 128
#define NN   256

// Fused v2 (resubmit, perturbed source): one block per (b, iblk of 64 rows,
// o-group of 4). 512 blocks x 256 threads.
//
// Phase 1: thread (ql = t>>6, j4 = t&63) computes float4 of
//   Pi[b, og*4+ql, 4*j4..+3] and Pj[...] via a 128-deep GEMV into smem.
//   node float4 loads are identical across the 4 ql's (L1 broadcast).
//
// Phase 2: thread (ql, j4) owns 16 rows; each 4-row adj group is loaded once
// into registers and reused across the 4 o's:
//   out[b,o,i,j] = adj[b,i,j] * (i==j ? Pi[o,j] : Pj[o,j])
// Output stores are evict-first (__stcs) so the 134MB stream doesn't evict
// hot adj/node lines from L2.
__global__ void __launch_bounds__(256)
fused_kernel(const float* __restrict__ node,
             const float* __restrict__ Wi,
             const float* __restrict__ Wj,
             const float4* __restrict__ adj,
             float4* __restrict__ out) {
    __shared__ __align__(16) float s_pi[4 * NN];
    __shared__ __align__(16) float s_pj[4 * NN];

    const int t  = threadIdx.x;                 // 0..255
    const int j4 = t & 63;                      // float4 column index
    const int ql = t >> 6;                      // 0..3

    const int og   = blockIdx.x & 31;           // o-group (fastest varying)
    const int iblk = (blockIdx.x >> 5) & 3;     // 64-row i-block
    const int b    = blockIdx.x >> 7;           // batch

    // ---------------- Phase 1: projections for o = og*4 + ql ----------------
    const float4* node4 = (const float4*)(node + b * NIN * NN);   // [c][j4]
    {
        const int o = (og << 2) + ql;
        const float* wi = Wi + o * NIN;
        const float* wj = Wj + o * NIN;

        float aix = 0.f, aiy = 0.f, aiz = 0.f, aiw = 0.f;
        float ajx = 0.f, ajy = 0.f, ajz = 0.f, ajw = 0.f;
#pragma unroll 8
        for (int c = 0; c < NIN; ++c) {
            const float4 nv = __ldg(&node4[(c << 6) + j4]);
            const float wiv = __ldg(&wi[c]);
            const float wjv = __ldg(&wj[c]);
            aix = fmaf(wiv, nv.x, aix); aiy = fmaf(wiv, nv.y, aiy);
            aiz = fmaf(wiv, nv.z, aiz); aiw = fmaf(wiv, nv.w, aiw);
            ajx = fmaf(wjv, nv.x, ajx); ajy = fmaf(wjv, nv.y, ajy);
            ajz = fmaf(wjv, nv.z, ajz); ajw = fmaf(wjv, nv.w, ajw);
        }
        reinterpret_cast<float4*>(s_pi)[(ql << 6) + j4] =
            make_float4(aix, aiy, aiz, aiw);
        reinterpret_cast<float4*>(s_pj)[(ql << 6) + j4] =
            make_float4(ajx, ajy, ajz, ajw);
    }
    __syncthreads();

    // ---------------- Phase 2: stream 64 rows x 4 o-images ----------------
    float4 P0 = reinterpret_cast<const float4*>(s_pj)[(0 << 6) + j4];
    float4 P1 = reinterpret_cast<const float4*>(s_pj)[(1 << 6) + j4];
    float4 P2 = reinterpret_cast<const float4*>(s_pj)[(2 << 6) + j4];
    float4 P3 = reinterpret_cast<const float4*>(s_pj)[(3 << 6) + j4];

    const float4* adj_b    = adj + ((unsigned)b << 14);
    float4*       out_base = out + (((unsigned)(b << 7) + (og << 2)) << 14);

    for (int g = 0; g < 4; ++g) {
        const int i0 = (iblk << 6) + (ql << 4) + (g << 2);   // 4-aligned rows

        const float4 a0 = __ldg(&adj_b[((i0 + 0) << 6) + j4]);
        const float4 a1 = __ldg(&adj_b[((i0 + 1) << 6) + j4]);
        const float4 a2 = __ldg(&adj_b[((i0 + 2) << 6) + j4]);
        const float4 a3 = __ldg(&adj_b[((i0 + 3) << 6) + j4]);

        const bool diag = ((i0 >> 2) == j4);

#pragma unroll
        for (int ol = 0; ol < 4; ++ol) {
            const float4 p = (ol == 0) ? P0 : (ol == 1) ? P1 : (ol == 2) ? P2 : P3;

            float4 r0, r1, r2, r3;
            r0.x = a0.x * p.x; r0.y = a0.y * p.y; r0.z = a0.z * p.z; r0.w = a0.w * p.w;
            r1.x = a1.x * p.x; r1.y = a1.y * p.y; r1.z = a1.z * p.z; r1.w = a1.w * p.w;
            r2.x = a2.x * p.x; r2.y = a2.y * p.y; r2.z = a2.z * p.z; r2.w = a2.w * p.w;
            r3.x = a3.x * p.x; r3.y = a3.y * p.y; r3.z = a3.z * p.z; r3.w = a3.w * p.w;

            if (diag) {   // rows i0..i0+3 hold diagonal elems at lanes 0..3
                r0.x = a0.x * s_pi[(ol << 8) + i0 + 0];
                r1.y = a1.y * s_pi[(ol << 8) + i0 + 1];
                r2.z = a2.z * s_pi[(ol << 8) + i0 + 2];
                r3.w = a3.w * s_pi[(ol << 8) + i0 + 3];
            }

            float4* dst = out_base + ((unsigned)ol << 14);
            __stcs(&dst[((i0 + 0) << 6) + j4], r0);
            __stcs(&dst[((i0 + 1) << 6) + j4], r1);
            __stcs(&dst[((i0 + 2) << 6) + j4], r2);
            __stcs(&dst[((i0 + 3) << 6) + j4], r3);
        }
    }
}

extern "C" void kernel_launch(void* const* d_in, const int* in_sizes, int n_in,
                              void* d_out, int out_size) {
    const float* adj  = (const float*)d_in[0];  // [B,1,N,N]
    const float* node = (const float*)d_in[1];  // [B,NIN,N]
    const float* Wi   = (const float*)d_in[2];  // [NOUT,NIN]
    const float* Wj   = (const float*)d_in[3];  // [NOUT,NIN]
    float* out = (float*)d_out;                 // [B,NOUT,N,N]

    (void)in_sizes; (void)n_in; (void)out_size;

    fused_kernel<<<BB * 4 * 32, 256>>>(node, Wi, Wj,
                                       (const float4*)adj, (float4*)out);
}